// round 4
// baseline (speedup 1.0000x reference)
#include <cuda_runtime.h>
#include <cuda_bf16.h>
#include <cstdint>
#include <math.h>

// Problem dims
#define T_DIM 1024
#define B_DIM 32
#define C_DIM 1024
#define K_DIM 1024
#define E_DIM 16
#define TBC   33554432  // T*B*C

// ---------------- device scratch (allocation-free rule: __device__ globals) -----
__device__ float                          g_resp[B_DIM * E_DIM];
__device__ __align__(256) __nv_bfloat16   g_xb[(size_t)T_DIM * B_DIM * C_DIM];  // 67MB
__device__ __align__(256) __nv_bfloat16   g_w [(size_t)B_DIM * C_DIM * C_DIM]; // 67MB

// ---------------- helpers -------------------------------------------------------
__device__ __forceinline__ uint32_t smem_u32(const void* p) {
    uint32_t a;
    asm("{ .reg .u64 t; cvta.to.shared.u64 t, %1; cvt.u32.u64 %0, t; }" : "=r"(a) : "l"(p));
    return a;
}
__device__ __forceinline__ void cp16(uint32_t dst, const void* src) {
    asm volatile("cp.async.cg.shared.global [%0], [%1], 16;" :: "r"(dst), "l"(src));
}
__device__ __forceinline__ void ldsm_x4(uint32_t* r, uint32_t addr) {
    asm volatile("ldmatrix.sync.aligned.m8n8.x4.shared.b16 {%0,%1,%2,%3}, [%4];"
                 : "=r"(r[0]), "=r"(r[1]), "=r"(r[2]), "=r"(r[3]) : "r"(addr));
}
__device__ __forceinline__ void mma16816(float* c, const uint32_t* a, const uint32_t* b) {
    asm volatile(
        "mma.sync.aligned.m16n8k16.row.col.f32.bf16.bf16.f32 "
        "{%0,%1,%2,%3}, {%4,%5,%6,%7}, {%8,%9}, {%0,%1,%2,%3};"
        : "+f"(c[0]), "+f"(c[1]), "+f"(c[2]), "+f"(c[3])
        : "r"(a[0]), "r"(a[1]), "r"(a[2]), "r"(a[3]), "r"(b[0]), "r"(b[1]));
}

// ================================================================================
// Kernel 1: routing — logits -> softmax -> g_resp, importance std/mean loss
// ================================================================================
__global__ void routing_kernel(const float* __restrict__ key,
                               const float* __restrict__ aw,
                               const float* __restrict__ ab,
                               float* __restrict__ out, int out_size) {
    __shared__ float sl[B_DIM][E_DIM];
    __shared__ float sr[B_DIM][E_DIM];
    int tid = threadIdx.x;            // 512 threads
    int b = tid >> 4, e = tid & 15;
    const float* kr = key + b * K_DIM;
    float a0 = 0.f, a1 = 0.f, a2 = 0.f, a3 = 0.f;
    #pragma unroll 4
    for (int k = 0; k < K_DIM; k += 4) {
        a0 = fmaf(kr[k],     aw[(k)     * E_DIM + e], a0);
        a1 = fmaf(kr[k + 1], aw[(k + 1) * E_DIM + e], a1);
        a2 = fmaf(kr[k + 2], aw[(k + 2) * E_DIM + e], a2);
        a3 = fmaf(kr[k + 3], aw[(k + 3) * E_DIM + e], a3);
    }
    sl[b][e] = (a0 + a1) + (a2 + a3) + ab[e];
    __syncthreads();
    if (tid < B_DIM) {
        int bb = tid;
        float mx = -1e30f;
        #pragma unroll
        for (int j = 0; j < E_DIM; j++) mx = fmaxf(mx, sl[bb][j]);
        float v[E_DIM];
        float s = 0.f;
        #pragma unroll
        for (int j = 0; j < E_DIM; j++) { v[j] = expf(sl[bb][j] - mx); s += v[j]; }
        float inv = 1.f / s;
        #pragma unroll
        for (int j = 0; j < E_DIM; j++) {
            float r = v[j] * inv;
            sr[bb][j] = r;
            g_resp[bb * E_DIM + j] = r;
        }
    }
    __syncthreads();
    if (tid == 0 && out_size > TBC) {
        float imp[E_DIM];
        float tot = 0.f;
        #pragma unroll
        for (int j = 0; j < E_DIM; j++) {
            float s = 0.f;
            for (int bb = 0; bb < B_DIM; bb++) s += sr[bb][j];
            imp[j] = s; tot += s;
        }
        float mean = tot / E_DIM;
        float var = 0.f;
        #pragma unroll
        for (int j = 0; j < E_DIM; j++) { float d = imp[j] - mean; var += d * d; }
        var /= (E_DIM - 1);
        out[out_size - 1] = 0.01f * sqrtf(var) / mean;
    }
}

// ================================================================================
// Kernel 2 (fused): blocks [0,16384): x fp32 -> bf16
//                   blocks [16384,16896): W[b] = sum_e resp[b,e] * pw_w1[e]
// Independent work, disjoint writes -> overlap the two memory-bound passes.
// ================================================================================
#define XCONV_BLOCKS 16384
#define WGEN_BLOCKS  512
__global__ void __launch_bounds__(512)
prep_kernel(const float4* __restrict__ x, const float4* __restrict__ pw) {
    if (blockIdx.x < XCONV_BLOCKS) {
        size_t i = (size_t)blockIdx.x * 512 + threadIdx.x;  // < 8388608
        float4 v = x[i];
        union { __nv_bfloat16 h[4]; uint2 u; } r;
        r.h[0] = __float2bfloat16(v.x);
        r.h[1] = __float2bfloat16(v.y);
        r.h[2] = __float2bfloat16(v.z);
        r.h[3] = __float2bfloat16(v.w);
        ((uint2*)g_xb)[i] = r.u;
    } else {
        __shared__ float sresp[B_DIM * E_DIM];
        sresp[threadIdx.x] = g_resp[threadIdx.x];   // 512 threads, 512 entries
        __syncthreads();
        size_t n4 = (size_t)(blockIdx.x - XCONV_BLOCKS) * 512 + threadIdx.x;  // < 262144
        float4 p[E_DIM];
        #pragma unroll
        for (int e = 0; e < E_DIM; e++) p[e] = pw[(size_t)e * 262144 + n4];
        for (int b = 0; b < B_DIM; b++) {
            float rx = 0.f, ry = 0.f, rz = 0.f, rw = 0.f;
            #pragma unroll
            for (int e = 0; e < E_DIM; e++) {
                float r = sresp[b * E_DIM + e];
                rx = fmaf(r, p[e].x, rx);
                ry = fmaf(r, p[e].y, ry);
                rz = fmaf(r, p[e].z, rz);
                rw = fmaf(r, p[e].w, rw);
            }
            union { __nv_bfloat16 h[4]; uint2 u; } o;
            o.h[0] = __float2bfloat16(rx);
            o.h[1] = __float2bfloat16(ry);
            o.h[2] = __float2bfloat16(rz);
            o.h[3] = __float2bfloat16(rw);
            ((uint2*)(g_w + (size_t)b * (C_DIM * C_DIM)))[n4] = o.u;
        }
    }
}

// ================================================================================
// Kernel 3: batched GEMM  Y_b = X_b @ W_b^T + residual  (mma.sync bf16, fp32 acc)
//   CTA 128x128, BK=32, 256 thr = 8 warps (2m x 4n), warp tile 64x32
//   3-stage cp.async pipeline, ONE __syncthreads per k-iteration
//   smem rows padded to 80B: conflict-free cp.async stores and ldmatrix reads
// ================================================================================
#define BM 128
#define BN 128
#define BK 32
#define PROW 80
#define NKC (C_DIM / BK)              // 32 k-chunks
#define NSTG 3

__device__ __forceinline__ void issue_tile(uint32_t da, uint32_t db,
                                           const __nv_bfloat16* Ag,
                                           const __nv_bfloat16* Bg,
                                           int ko, int r0c, int r1c, int cc) {
    cp16(da + r0c * PROW + cc * 16, Ag + (size_t)r0c * (B_DIM * C_DIM) + ko + cc * 8);
    cp16(da + r1c * PROW + cc * 16, Ag + (size_t)r1c * (B_DIM * C_DIM) + ko + cc * 8);
    cp16(db + r0c * PROW + cc * 16, Bg + (size_t)r0c * C_DIM + ko + cc * 8);
    cp16(db + r1c * PROW + cc * 16, Bg + (size_t)r1c * C_DIM + ko + cc * 8);
}

__global__ void __launch_bounds__(256, 2)
gemm_kernel(const float* __restrict__ x, float* __restrict__ out) {
    __shared__ __align__(16) char smA[NSTG][BM * PROW];
    __shared__ __align__(16) char smB[NSTG][BN * PROW];

    const int tid = threadIdx.x;
    const int lane = tid & 31, wid = tid >> 5;
    const int wm = wid >> 2;          // 0..1  (64 rows each)
    const int wn = wid & 3;           // 0..3  (32 cols each)
    const int o0 = blockIdx.x * BN;
    const int t0 = blockIdx.y * BM;
    const int b  = blockIdx.z;

    const __nv_bfloat16* Ag = g_xb + ((size_t)t0 * B_DIM + b) * C_DIM;       // row stride B*C
    const __nv_bfloat16* Bg = g_w  + ((size_t)b * C_DIM + o0) * C_DIM;       // row stride C

    uint32_t sAb[NSTG], sBb[NSTG];
    #pragma unroll
    for (int s = 0; s < NSTG; s++) { sAb[s] = smem_u32(smA[s]); sBb[s] = smem_u32(smB[s]); }

    // load thread mapping: 512 16B chunks per tile -> 2 per thread
    const int r0c = tid >> 2, cc = tid & 3;
    const int r1c = r0c + 64;

    float acc[4][4][4];
    #pragma unroll
    for (int i = 0; i < 4; i++)
        #pragma unroll
        for (int j = 0; j < 4; j++)
            #pragma unroll
            for (int q = 0; q < 4; q++) acc[i][j][q] = 0.f;

    // ldmatrix address components
    const int a_row = lane & 15;
    const int a_col = (lane >> 4) * 8;
    const int bq = lane >> 3;
    const int b_row = (bq >> 1) * 8 + (lane & 7);
    const int b_col = (bq & 1) * 8;

    // prologue: stages 0,1
    issue_tile(sAb[0], sBb[0], Ag, Bg, 0, r0c, r1c, cc);
    asm volatile("cp.async.commit_group;" ::: "memory");
    issue_tile(sAb[1], sBb[1], Ag, Bg, BK, r0c, r1c, cc);
    asm volatile("cp.async.commit_group;" ::: "memory");

    int ic = 0;                        // compute stage index (kc % 3)
    #pragma unroll 1
    for (int kc = 0; kc < NKC; kc++) {
        asm volatile("cp.async.wait_group 1;" ::: "memory");  // buf ic ready
        __syncthreads();               // + everyone finished reading buf (kc-1)%3

        int wt = kc + NSTG - 1;        // tile to prefetch into the freed buffer
        if (wt < NKC) {
            int iw = ic + (NSTG - 1); if (iw >= NSTG) iw -= NSTG;
            issue_tile(sAb[iw], sBb[iw], Ag, Bg, wt * BK, r0c, r1c, cc);
        }
        asm volatile("cp.async.commit_group;" ::: "memory");

        uint32_t Ab = sAb[ic] + (uint32_t)(wm * 64) * PROW;
        uint32_t Bb = sBb[ic] + (uint32_t)(wn * 32) * PROW;
        #pragma unroll
        for (int ks = 0; ks < 2; ks++) {
            uint32_t af[4][4];
            #pragma unroll
            for (int mt = 0; mt < 4; mt++)
                ldsm_x4(af[mt], Ab + (uint32_t)(mt * 16 + a_row) * PROW + (a_col + ks * 16) * 2);
            uint32_t bf[4][2];
            #pragma unroll
            for (int nt2 = 0; nt2 < 2; nt2++) {
                uint32_t t4[4];
                ldsm_x4(t4, Bb + (uint32_t)(nt2 * 16 + b_row) * PROW + (b_col + ks * 16) * 2);
                bf[nt2 * 2][0] = t4[0]; bf[nt2 * 2][1] = t4[1];
                bf[nt2 * 2 + 1][0] = t4[2]; bf[nt2 * 2 + 1][1] = t4[3];
            }
            #pragma unroll
            for (int mt = 0; mt < 4; mt++)
                #pragma unroll
                for (int nt = 0; nt < 4; nt++)
                    mma16816(acc[mt][nt], af[mt], bf[nt]);
        }
        ic++; if (ic == NSTG) ic = 0;
    }

    // epilogue: fused residual add, fp32 out
    const int erow = lane >> 2;
    const int ecol = (lane & 3) * 2;
    #pragma unroll
    for (int mt = 0; mt < 4; mt++) {
        int t_lo = t0 + wm * 64 + mt * 16 + erow;
        #pragma unroll
        for (int nt = 0; nt < 4; nt++) {
            int o = o0 + wn * 32 + nt * 8 + ecol;
            size_t i0 = ((size_t)t_lo * B_DIM + b) * C_DIM + o;
            size_t i1 = i0 + (size_t)8 * B_DIM * C_DIM;   // t_lo + 8
            float2 x0 = *(const float2*)(x + i0);
            float2 x1 = *(const float2*)(x + i1);
            float2 y0, y1;
            y0.x = x0.x + acc[mt][nt][0];
            y0.y = x0.y + acc[mt][nt][1];
            y1.x = x1.x + acc[mt][nt][2];
            y1.y = x1.y + acc[mt][nt][3];
            *(float2*)(out + i0) = y0;
            *(float2*)(out + i1) = y1;
        }
    }
}

// ================================================================================
extern "C" void kernel_launch(void* const* d_in, const int* in_sizes, int n_in,
                              void* d_out, int out_size) {
    const float* x   = (const float*)d_in[0];
    const float* key = (const float*)d_in[1];
    const float* aw  = (const float*)d_in[2];
    const float* ab  = (const float*)d_in[3];
    const float* pw  = (const float*)d_in[4];
    float* out = (float*)d_out;

    routing_kernel<<<1, 512>>>(key, aw, ab, out, out_size);
    prep_kernel<<<XCONV_BLOCKS + WGEN_BLOCKS, 512>>>((const float4*)x, (const float4*)pw);
    gemm_kernel<<<dim3(C_DIM / BN, T_DIM / BM, B_DIM), 256>>>(x, out);
}

// round 5
// speedup vs baseline: 1.3422x; 1.3422x over previous
#include <cuda_runtime.h>
#include <cuda_bf16.h>
#include <cstdint>
#include <math.h>

// Problem dims
#define T_DIM 1024
#define B_DIM 32
#define C_DIM 1024
#define K_DIM 1024
#define E_DIM 16
#define TBC   33554432  // T*B*C

// ---------------- device scratch (allocation-free rule: __device__ globals) -----
__device__ float                          g_resp[B_DIM * E_DIM];
__device__ __align__(256) __nv_bfloat16   g_xb[(size_t)T_DIM * B_DIM * C_DIM];  // 67MB
__device__ __align__(256) __nv_bfloat16   g_w [(size_t)B_DIM * C_DIM * C_DIM]; // 67MB

// ---------------- helpers -------------------------------------------------------
__device__ __forceinline__ uint32_t smem_u32(const void* p) {
    uint32_t a;
    asm("{ .reg .u64 t; cvta.to.shared.u64 t, %1; cvt.u32.u64 %0, t; }" : "=r"(a) : "l"(p));
    return a;
}
__device__ __forceinline__ void cp16(uint32_t dst, const void* src) {
    asm volatile("cp.async.cg.shared.global [%0], [%1], 16;" :: "r"(dst), "l"(src));
}
__device__ __forceinline__ void ldsm_x4(uint32_t* r, uint32_t addr) {
    asm volatile("ldmatrix.sync.aligned.m8n8.x4.shared.b16 {%0,%1,%2,%3}, [%4];"
                 : "=r"(r[0]), "=r"(r[1]), "=r"(r[2]), "=r"(r[3]) : "r"(addr));
}
__device__ __forceinline__ void mma16816(float* c, const uint32_t* a, const uint32_t* b) {
    asm volatile(
        "mma.sync.aligned.m16n8k16.row.col.f32.bf16.bf16.f32 "
        "{%0,%1,%2,%3}, {%4,%5,%6,%7}, {%8,%9}, {%0,%1,%2,%3};"
        : "+f"(c[0]), "+f"(c[1]), "+f"(c[2]), "+f"(c[3])
        : "r"(a[0]), "r"(a[1]), "r"(a[2]), "r"(a[3]), "r"(b[0]), "r"(b[1]));
}

// ================================================================================
// Kernel 1: routing — one block per batch element; warp w computes logit (b, e=w)
// ================================================================================
__global__ void __launch_bounds__(512)
routing_kernel(const float* __restrict__ key,
               const float* __restrict__ aw,
               const float* __restrict__ ab) {
    __shared__ float slog[E_DIM];
    const int b = blockIdx.x;
    const int lane = threadIdx.x & 31;
    const int e = threadIdx.x >> 5;          // 16 warps = 16 experts
    const float* kr = key + b * K_DIM;

    float acc = 0.f;
    #pragma unroll 8
    for (int k = lane; k < K_DIM; k += 32)
        acc = fmaf(kr[k], aw[k * E_DIM + e], acc);
    #pragma unroll
    for (int off = 16; off > 0; off >>= 1)
        acc += __shfl_xor_sync(0xFFFFFFFF, acc, off);
    if (lane == 0) slog[e] = acc + ab[e];
    __syncthreads();

    if (threadIdx.x == 0) {
        float mx = -1e30f;
        #pragma unroll
        for (int j = 0; j < E_DIM; j++) mx = fmaxf(mx, slog[j]);
        float v[E_DIM]; float s = 0.f;
        #pragma unroll
        for (int j = 0; j < E_DIM; j++) { v[j] = expf(slog[j] - mx); s += v[j]; }
        float inv = 1.f / s;
        #pragma unroll
        for (int j = 0; j < E_DIM; j++) g_resp[b * E_DIM + j] = v[j] * inv;
    }
}

// ================================================================================
// Kernel 2: x fp32 -> bf16 (same layout)
// ================================================================================
__global__ void xconv_kernel(const float4* __restrict__ x) {
    size_t i = (size_t)blockIdx.x * blockDim.x + threadIdx.x;  // < 8388608
    float4 v = x[i];
    union { __nv_bfloat16 h[4]; uint2 u; } r;
    r.h[0] = __float2bfloat16(v.x);
    r.h[1] = __float2bfloat16(v.y);
    r.h[2] = __float2bfloat16(v.z);
    r.h[3] = __float2bfloat16(v.w);
    ((uint2*)g_xb)[i] = r.u;
}

// ================================================================================
// Kernel 3: W[b] = sum_e resp[b,e] * pw_w1[e]; block 0 also emits the loss scalar
// ================================================================================
__global__ void wgen_kernel(const float4* __restrict__ pw,
                            float* __restrict__ out, int out_size) {
    __shared__ float sresp[B_DIM * E_DIM];
    for (int i = threadIdx.x; i < B_DIM * E_DIM; i += blockDim.x)
        sresp[i] = g_resp[i];
    __syncthreads();

    if (blockIdx.x == 0 && threadIdx.x == 0 && out_size > TBC) {
        float imp[E_DIM]; float tot = 0.f;
        #pragma unroll
        for (int j = 0; j < E_DIM; j++) {
            float s = 0.f;
            for (int bb = 0; bb < B_DIM; bb++) s += sresp[bb * E_DIM + j];
            imp[j] = s; tot += s;
        }
        float mean = tot / E_DIM;
        float var = 0.f;
        #pragma unroll
        for (int j = 0; j < E_DIM; j++) { float d = imp[j] - mean; var += d * d; }
        var /= (E_DIM - 1);
        out[out_size - 1] = 0.01f * sqrtf(var) / mean;
    }

    size_t n4 = (size_t)blockIdx.x * blockDim.x + threadIdx.x;  // < 262144 (= C*C/4)
    float4 p[E_DIM];
    #pragma unroll
    for (int e = 0; e < E_DIM; e++) p[e] = pw[(size_t)e * 262144 + n4];
    for (int b = 0; b < B_DIM; b++) {
        float rx = 0.f, ry = 0.f, rz = 0.f, rw = 0.f;
        #pragma unroll
        for (int e = 0; e < E_DIM; e++) {
            float r = sresp[b * E_DIM + e];
            rx = fmaf(r, p[e].x, rx);
            ry = fmaf(r, p[e].y, ry);
            rz = fmaf(r, p[e].z, rz);
            rw = fmaf(r, p[e].w, rw);
        }
        union { __nv_bfloat16 h[4]; uint2 u; } o;
        o.h[0] = __float2bfloat16(rx);
        o.h[1] = __float2bfloat16(ry);
        o.h[2] = __float2bfloat16(rz);
        o.h[3] = __float2bfloat16(rw);
        ((uint2*)(g_w + (size_t)b * (C_DIM * C_DIM)))[n4] = o.u;
    }
}

// ================================================================================
// Kernel 4: batched GEMM  Y_b = X_b @ W_b^T + residual  (mma.sync bf16, fp32 acc)
//   CTA tile 128x128, BK=32, 256 threads = 8 warps (2 m x 4 n), warp tile 64x32
//   2-stage double buffer (R3-measured config)
// ================================================================================
#define BM 128
#define BN 128
#define BK 32
#define PROW 80                       // bytes per padded smem row (32 bf16 -> 80B)
#define NKC (C_DIM / BK)              // 32 k-chunks

__global__ void __launch_bounds__(256, 2)
gemm_kernel(const float* __restrict__ x, float* __restrict__ out) {
    __shared__ __align__(16) char smA[2][BM * PROW];
    __shared__ __align__(16) char smB[2][BN * PROW];

    const int tid = threadIdx.x;
    const int lane = tid & 31, wid = tid >> 5;
    const int wm = wid >> 2;          // 0..1  (64 rows each)
    const int wn = wid & 3;           // 0..3  (32 cols each)
    const int o0 = blockIdx.x * BN;
    const int t0 = blockIdx.y * BM;
    const int b  = blockIdx.z;

    const __nv_bfloat16* Ag = g_xb + ((size_t)t0 * B_DIM + b) * C_DIM;       // row stride B*C
    const __nv_bfloat16* Bg = g_w  + ((size_t)b * C_DIM + o0) * C_DIM;       // row stride C

    const uint32_t sA0 = smem_u32(smA[0]), sA1 = smem_u32(smA[1]);
    const uint32_t sB0 = smem_u32(smB[0]), sB1 = smem_u32(smB[1]);

    // load thread mapping: 512 16B chunks per tile -> 2 per thread
    const int r0c = tid >> 2, c0c = tid & 3;
    const int r1c = (tid + 256) >> 2, c1c = tid & 3;

    float acc[4][4][4];
    #pragma unroll
    for (int i = 0; i < 4; i++)
        #pragma unroll
        for (int j = 0; j < 4; j++)
            #pragma unroll
            for (int q = 0; q < 4; q++) acc[i][j][q] = 0.f;

    // ldmatrix address components
    const int a_row = lane & 15;
    const int a_col = (lane >> 4) * 8;
    const int bq = lane >> 3;
    const int b_row = (bq >> 1) * 8 + (lane & 7);
    const int b_col = (bq & 1) * 8;

    // prologue: stage 0
    {
        uint32_t da = sA0, db = sB0;
        cp16(da + r0c * PROW + c0c * 16, Ag + (size_t)r0c * (B_DIM * C_DIM) + c0c * 8);
        cp16(da + r1c * PROW + c1c * 16, Ag + (size_t)r1c * (B_DIM * C_DIM) + c1c * 8);
        cp16(db + r0c * PROW + c0c * 16, Bg + (size_t)r0c * C_DIM + c0c * 8);
        cp16(db + r1c * PROW + c1c * 16, Bg + (size_t)r1c * C_DIM + c1c * 8);
        asm volatile("cp.async.commit_group;" ::: "memory");
    }

    for (int kc = 0; kc < NKC; kc++) {
        if (kc + 1 < NKC) {
            int nb = (kc + 1) & 1;
            uint32_t da = nb ? sA1 : sA0, db = nb ? sB1 : sB0;
            int ko = (kc + 1) * BK;
            cp16(da + r0c * PROW + c0c * 16, Ag + (size_t)r0c * (B_DIM * C_DIM) + ko + c0c * 8);
            cp16(da + r1c * PROW + c1c * 16, Ag + (size_t)r1c * (B_DIM * C_DIM) + ko + c1c * 8);
            cp16(db + r0c * PROW + c0c * 16, Bg + (size_t)r0c * C_DIM + ko + c0c * 8);
            cp16(db + r1c * PROW + c1c * 16, Bg + (size_t)r1c * C_DIM + ko + c1c * 8);
            asm volatile("cp.async.commit_group;" ::: "memory");
            asm volatile("cp.async.wait_group 1;" ::: "memory");
        } else {
            asm volatile("cp.async.wait_group 0;" ::: "memory");
        }
        __syncthreads();

        int buf = kc & 1;
        uint32_t Ab = (buf ? sA1 : sA0) + (uint32_t)(wm * 64) * PROW;
        uint32_t Bb = (buf ? sB1 : sB0) + (uint32_t)(wn * 32) * PROW;

        #pragma unroll
        for (int ks = 0; ks < 2; ks++) {
            uint32_t af[4][4];
            #pragma unroll
            for (int mt = 0; mt < 4; mt++)
                ldsm_x4(af[mt], Ab + (uint32_t)(mt * 16 + a_row) * PROW + (a_col + ks * 16) * 2);
            uint32_t bf[4][2];
            #pragma unroll
            for (int nt2 = 0; nt2 < 2; nt2++) {
                uint32_t t4[4];
                ldsm_x4(t4, Bb + (uint32_t)(nt2 * 16 + b_row) * PROW + (b_col + ks * 16) * 2);
                bf[nt2 * 2][0] = t4[0]; bf[nt2 * 2][1] = t4[1];
                bf[nt2 * 2 + 1][0] = t4[2]; bf[nt2 * 2 + 1][1] = t4[3];
            }
            #pragma unroll
            for (int mt = 0; mt < 4; mt++)
                #pragma unroll
                for (int nt = 0; nt < 4; nt++)
                    mma16816(acc[mt][nt], af[mt], bf[nt]);
        }
        __syncthreads();
    }

    // epilogue: fused residual add, fp32 out
    const int erow = lane >> 2;
    const int ecol = (lane & 3) * 2;
    #pragma unroll
    for (int mt = 0; mt < 4; mt++) {
        int t_lo = t0 + wm * 64 + mt * 16 + erow;
        #pragma unroll
        for (int nt = 0; nt < 4; nt++) {
            int o = o0 + wn * 32 + nt * 8 + ecol;
            size_t i0 = ((size_t)t_lo * B_DIM + b) * C_DIM + o;
            size_t i1 = i0 + (size_t)8 * B_DIM * C_DIM;   // t_lo + 8
            float2 x0 = *(const float2*)(x + i0);
            float2 x1 = *(const float2*)(x + i1);
            float2 y0, y1;
            y0.x = x0.x + acc[mt][nt][0];
            y0.y = x0.y + acc[mt][nt][1];
            y1.x = x1.x + acc[mt][nt][2];
            y1.y = x1.y + acc[mt][nt][3];
            *(float2*)(out + i0) = y0;
            *(float2*)(out + i1) = y1;
        }
    }
}

// ================================================================================
extern "C" void kernel_launch(void* const* d_in, const int* in_sizes, int n_in,
                              void* d_out, int out_size) {
    const float* x   = (const float*)d_in[0];
    const float* key = (const float*)d_in[1];
    const float* aw  = (const float*)d_in[2];
    const float* ab  = (const float*)d_in[3];
    const float* pw  = (const float*)d_in[4];
    float* out = (float*)d_out;

    routing_kernel<<<B_DIM, 512>>>(key, aw, ab);
    xconv_kernel<<<16384, 512>>>((const float4*)x);          // 8388608 float4s
    wgen_kernel<<<1024, 256>>>((const float4*)pw, out, out_size);
    gemm_kernel<<<dim3(C_DIM / BN, T_DIM / BM, B_DIM), 256>>>(x, out);
}

// round 6
// speedup vs baseline: 1.4349x; 1.0691x over previous
#include <cuda_runtime.h>
#include <cuda_bf16.h>
#include <cstdint>
#include <math.h>

// Problem dims
#define T_DIM 1024
#define B_DIM 32
#define C_DIM 1024
#define K_DIM 1024
#define E_DIM 16
#define TBC   33554432  // T*B*C

// ---------------- device scratch (allocation-free rule: __device__ globals) -----
__device__ float                          g_resp[B_DIM * E_DIM];
__device__ __align__(256) __nv_bfloat16   g_xb[(size_t)T_DIM * B_DIM * C_DIM];  // 67MB
__device__ __align__(256) __nv_bfloat16   g_w [(size_t)B_DIM * C_DIM * C_DIM]; // 67MB

// ---------------- helpers -------------------------------------------------------
__device__ __forceinline__ uint32_t smem_u32(const void* p) {
    uint32_t a;
    asm("{ .reg .u64 t; cvta.to.shared.u64 t, %1; cvt.u32.u64 %0, t; }" : "=r"(a) : "l"(p));
    return a;
}
__device__ __forceinline__ void cp16(uint32_t dst, const void* src) {
    asm volatile("cp.async.cg.shared.global [%0], [%1], 16;" :: "r"(dst), "l"(src));
}
__device__ __forceinline__ void ldsm_x4(uint32_t* r, uint32_t addr) {
    asm volatile("ldmatrix.sync.aligned.m8n8.x4.shared.b16 {%0,%1,%2,%3}, [%4];"
                 : "=r"(r[0]), "=r"(r[1]), "=r"(r[2]), "=r"(r[3]) : "r"(addr));
}
__device__ __forceinline__ void mma16816(float* c, const uint32_t* a, const uint32_t* b) {
    asm volatile(
        "mma.sync.aligned.m16n8k16.row.col.f32.bf16.bf16.f32 "
        "{%0,%1,%2,%3}, {%4,%5,%6,%7}, {%8,%9}, {%0,%1,%2,%3};"
        : "+f"(c[0]), "+f"(c[1]), "+f"(c[2]), "+f"(c[3])
        : "r"(a[0]), "r"(a[1]), "r"(a[2]), "r"(a[3]), "r"(b[0]), "r"(b[1]));
}

// ================================================================================
// Kernel 1: routing — one block per batch element; warp w computes logit (b, e=w)
// ================================================================================
__global__ void __launch_bounds__(512)
routing_kernel(const float* __restrict__ key,
               const float* __restrict__ aw,
               const float* __restrict__ ab) {
    __shared__ float slog[E_DIM];
    const int b = blockIdx.x;
    const int lane = threadIdx.x & 31;
    const int e = threadIdx.x >> 5;          // 16 warps = 16 experts
    const float* kr = key + b * K_DIM;

    float acc = 0.f;
    #pragma unroll 8
    for (int k = lane; k < K_DIM; k += 32)
        acc = fmaf(kr[k], aw[k * E_DIM + e], acc);
    #pragma unroll
    for (int off = 16; off > 0; off >>= 1)
        acc += __shfl_xor_sync(0xFFFFFFFF, acc, off);
    if (lane == 0) slog[e] = acc + ab[e];
    __syncthreads();

    if (threadIdx.x == 0) {
        float mx = -1e30f;
        #pragma unroll
        for (int j = 0; j < E_DIM; j++) mx = fmaxf(mx, slog[j]);
        float v[E_DIM]; float s = 0.f;
        #pragma unroll
        for (int j = 0; j < E_DIM; j++) { v[j] = expf(slog[j] - mx); s += v[j]; }
        float inv = 1.f / s;
        #pragma unroll
        for (int j = 0; j < E_DIM; j++) g_resp[b * E_DIM + j] = v[j] * inv;
    }
}

// ================================================================================
// Kernel 2: x fp32 -> bf16 (same layout)
// ================================================================================
__global__ void xconv_kernel(const float4* __restrict__ x) {
    size_t i = (size_t)blockIdx.x * blockDim.x + threadIdx.x;  // < 8388608
    float4 v = x[i];
    union { __nv_bfloat16 h[4]; uint2 u; } r;
    r.h[0] = __float2bfloat16(v.x);
    r.h[1] = __float2bfloat16(v.y);
    r.h[2] = __float2bfloat16(v.z);
    r.h[3] = __float2bfloat16(v.w);
    ((uint2*)g_xb)[i] = r.u;
}

// ================================================================================
// Kernel 3: W[b] = sum_e resp[b,e] * pw_w1[e]; block 0 also emits the loss scalar
// ================================================================================
__global__ void wgen_kernel(const float4* __restrict__ pw,
                            float* __restrict__ out, int out_size) {
    __shared__ float sresp[B_DIM * E_DIM];
    for (int i = threadIdx.x; i < B_DIM * E_DIM; i += blockDim.x)
        sresp[i] = g_resp[i];
    __syncthreads();

    if (blockIdx.x == 0 && threadIdx.x == 0 && out_size > TBC) {
        float imp[E_DIM]; float tot = 0.f;
        #pragma unroll
        for (int j = 0; j < E_DIM; j++) {
            float s = 0.f;
            for (int bb = 0; bb < B_DIM; bb++) s += sresp[bb * E_DIM + j];
            imp[j] = s; tot += s;
        }
        float mean = tot / E_DIM;
        float var = 0.f;
        #pragma unroll
        for (int j = 0; j < E_DIM; j++) { float d = imp[j] - mean; var += d * d; }
        var /= (E_DIM - 1);
        out[out_size - 1] = 0.01f * sqrtf(var) / mean;
    }

    size_t n4 = (size_t)blockIdx.x * blockDim.x + threadIdx.x;  // < 262144 (= C*C/4)
    float4 p[E_DIM];
    #pragma unroll
    for (int e = 0; e < E_DIM; e++) p[e] = pw[(size_t)e * 262144 + n4];
    for (int b = 0; b < B_DIM; b++) {
        float rx = 0.f, ry = 0.f, rz = 0.f, rw = 0.f;
        #pragma unroll
        for (int e = 0; e < E_DIM; e++) {
            float r = sresp[b * E_DIM + e];
            rx = fmaf(r, p[e].x, rx);
            ry = fmaf(r, p[e].y, ry);
            rz = fmaf(r, p[e].z, rz);
            rw = fmaf(r, p[e].w, rw);
        }
        union { __nv_bfloat16 h[4]; uint2 u; } o;
        o.h[0] = __float2bfloat16(rx);
        o.h[1] = __float2bfloat16(ry);
        o.h[2] = __float2bfloat16(rz);
        o.h[3] = __float2bfloat16(rw);
        ((uint2*)(g_w + (size_t)b * (C_DIM * C_DIM)))[n4] = o.u;
    }
}

// ================================================================================
// Kernel 4: batched GEMM  Y_b = X_b @ W_b^T + residual  (mma.sync bf16, fp32 acc)
//   CTA tile 128x128, BK=64, 256 threads = 8 warps (2m x 4n), warp tile 64x32
//   3-stage cp.async pipeline, ONE __syncthreads per k-iteration (16 iters)
//   PROW=144 (9 x 16B): ldmatrix phases conflict-free (row stride = 1 mod 8 segs)
// ================================================================================
#define BM 128
#define BN 128
#define BK 64
#define PROW 144
#define NKC (C_DIM / BK)              // 16 k-chunks
#define NSTG 3
#define A_STAGE (BM * PROW)           // 18432
#define STAGE_BYTES ((BM + BN) * PROW) // 36864
#define SMEM_BYTES (NSTG * STAGE_BYTES) // 110592

__device__ __forceinline__ void issue_tile(uint32_t abuf, uint32_t bbuf,
                                           const __nv_bfloat16* Ag,
                                           const __nv_bfloat16* Bg,
                                           int ko, int tid) {
    #pragma unroll
    for (int i = 0; i < 4; i++) {
        int idx = tid + i * 256;          // 0..1023
        int r = idx >> 3, c = idx & 7;    // 128 rows x 8 x 16B
        cp16(abuf + r * PROW + c * 16, Ag + (size_t)r * (B_DIM * C_DIM) + ko + c * 8);
        cp16(bbuf + r * PROW + c * 16, Bg + (size_t)r * C_DIM + ko + c * 8);
    }
}

__global__ void __launch_bounds__(256, 2)
gemm_kernel(const float* __restrict__ x, float* __restrict__ out) {
    extern __shared__ __align__(16) char smem[];

    const int tid = threadIdx.x;
    const int lane = tid & 31, wid = tid >> 5;
    const int wm = wid >> 2;          // 0..1  (64 rows each)
    const int wn = wid & 3;           // 0..3  (32 cols each)
    const int o0 = blockIdx.x * BN;
    const int t0 = blockIdx.y * BM;
    const int b  = blockIdx.z;

    const __nv_bfloat16* Ag = g_xb + ((size_t)t0 * B_DIM + b) * C_DIM;       // row stride B*C
    const __nv_bfloat16* Bg = g_w  + ((size_t)b * C_DIM + o0) * C_DIM;       // row stride C

    uint32_t sA[NSTG], sB[NSTG];
    {
        uint32_t base = smem_u32(smem);
        #pragma unroll
        for (int s = 0; s < NSTG; s++) {
            sA[s] = base + s * STAGE_BYTES;
            sB[s] = base + s * STAGE_BYTES + A_STAGE;
        }
    }

    float acc[4][4][4];
    #pragma unroll
    for (int i = 0; i < 4; i++)
        #pragma unroll
        for (int j = 0; j < 4; j++)
            #pragma unroll
            for (int q = 0; q < 4; q++) acc[i][j][q] = 0.f;

    // ldmatrix address components
    const int a_row = lane & 15;
    const int a_col = (lane >> 4) * 8;
    const int bq = lane >> 3;
    const int b_row = (bq >> 1) * 8 + (lane & 7);
    const int b_col = (bq & 1) * 8;

    // prologue: stages 0,1
    issue_tile(sA[0], sB[0], Ag, Bg, 0, tid);
    asm volatile("cp.async.commit_group;" ::: "memory");
    issue_tile(sA[1], sB[1], Ag, Bg, BK, tid);
    asm volatile("cp.async.commit_group;" ::: "memory");

    int ic = 0;                        // compute stage index (kc % 3)
    #pragma unroll 1
    for (int kc = 0; kc < NKC; kc++) {
        asm volatile("cp.async.wait_group 1;" ::: "memory");  // buf ic ready
        __syncthreads();               // + everyone done reading buf (kc-1)%3

        int wt = kc + NSTG - 1;        // tile to prefetch into the freed buffer
        if (wt < NKC) {
            int iw = ic + (NSTG - 1); if (iw >= NSTG) iw -= NSTG;
            issue_tile(sA[iw], sB[iw], Ag, Bg, wt * BK, tid);
        }
        asm volatile("cp.async.commit_group;" ::: "memory");

        uint32_t Ab = sA[ic] + (uint32_t)(wm * 64) * PROW;
        uint32_t Bb = sB[ic] + (uint32_t)(wn * 32) * PROW;
        #pragma unroll
        for (int ks = 0; ks < 4; ks++) {
            uint32_t af[4][4];
            #pragma unroll
            for (int mt = 0; mt < 4; mt++)
                ldsm_x4(af[mt], Ab + (uint32_t)(mt * 16 + a_row) * PROW + (a_col + ks * 16) * 2);
            uint32_t bf[4][2];
            #pragma unroll
            for (int nt2 = 0; nt2 < 2; nt2++) {
                uint32_t t4[4];
                ldsm_x4(t4, Bb + (uint32_t)(nt2 * 16 + b_row) * PROW + (b_col + ks * 16) * 2);
                bf[nt2 * 2][0] = t4[0]; bf[nt2 * 2][1] = t4[1];
                bf[nt2 * 2 + 1][0] = t4[2]; bf[nt2 * 2 + 1][1] = t4[3];
            }
            #pragma unroll
            for (int mt = 0; mt < 4; mt++)
                #pragma unroll
                for (int nt = 0; nt < 4; nt++)
                    mma16816(acc[mt][nt], af[mt], bf[nt]);
        }
        ic++; if (ic == NSTG) ic = 0;
    }

    // epilogue: fused residual add, fp32 out
    const int erow = lane >> 2;
    const int ecol = (lane & 3) * 2;
    #pragma unroll
    for (int mt = 0; mt < 4; mt++) {
        int t_lo = t0 + wm * 64 + mt * 16 + erow;
        #pragma unroll
        for (int nt = 0; nt < 4; nt++) {
            int o = o0 + wn * 32 + nt * 8 + ecol;
            size_t i0 = ((size_t)t_lo * B_DIM + b) * C_DIM + o;
            size_t i1 = i0 + (size_t)8 * B_DIM * C_DIM;   // t_lo + 8
            float2 x0 = *(const float2*)(x + i0);
            float2 x1 = *(const float2*)(x + i1);
            float2 y0, y1;
            y0.x = x0.x + acc[mt][nt][0];
            y0.y = x0.y + acc[mt][nt][1];
            y1.x = x1.x + acc[mt][nt][2];
            y1.y = x1.y + acc[mt][nt][3];
            *(float2*)(out + i0) = y0;
            *(float2*)(out + i1) = y1;
        }
    }
}

// ================================================================================
extern "C" void kernel_launch(void* const* d_in, const int* in_sizes, int n_in,
                              void* d_out, int out_size) {
    const float* x   = (const float*)d_in[0];
    const float* key = (const float*)d_in[1];
    const float* aw  = (const float*)d_in[2];
    const float* ab  = (const float*)d_in[3];
    const float* pw  = (const float*)d_in[4];
    float* out = (float*)d_out;

    cudaFuncSetAttribute(gemm_kernel, cudaFuncAttributeMaxDynamicSharedMemorySize, SMEM_BYTES);

    routing_kernel<<<B_DIM, 512>>>(key, aw, ab);
    xconv_kernel<<<16384, 512>>>((const float4*)x);          // 8388608 float4s
    wgen_kernel<<<1024, 256>>>((const float4*)pw, out, out_size);
    gemm_kernel<<<dim3(C_DIM / BN, T_DIM / BM, B_DIM), 256, SMEM_BYTES>>>(x, out);
}